// round 8
// baseline (speedup 1.0000x reference)
#include <cuda_runtime.h>
#include <cuda_fp16.h>
#include <cstdint>

// WeightedConvTranspose via mma.sync (fp16 m16n8k16, fp32 accum), parity-decomposed.
// R8: 2-product scheme — x split into fp16 hi+lo (captures ~22 mantissa bits),
// W single fp16 (rel err ~2^-12, well under 1e-3). B traffic halved vs bf16
// 3-product; A-fragments register-cached across the two taps sharing an x offset.
// Radial weight we[j,p] applied in fp32 on the per-tap accumulator.

#define B_       8
#define NIN_     16384
#define LOUT_    32768
#define PT_      128
#define THREADS_ 512
#define TILES_   (B_ * (NIN_ / PT_))   // 1024

#define XP_      66
#define CSP_     264

// ---- SMEM layout (bytes) ----
#define OFF_W    0                      // 9 chunks x 8192 (fp16 W) = 73728
#define WCH_(j)  (OFF_W + (j) * 8192)
#define OFF_XHI  73728                  // 132 rows x 128B = 16896
#define OFF_XLO  (OFF_XHI + 16896)      // 90624
#define OFF_X    (OFF_XLO + 16896)      // 107520: fp32 stage 132*66*4 = 34848
#define OFF_CS   (OFF_X + 34848)        // 142368: 3*264*4 = 3168
#define OFF_WE   (OFF_CS + 3168)        // 145536: 9*128*4 = 4608
#define SMEM_BYTES (OFF_WE + 4608)      // 150144

static __device__ __forceinline__ uint32_t smem_u32(const void* p) {
    uint32_t a;
    asm("{ .reg .u64 t; cvta.to.shared.u64 t, %1; cvt.u32.u64 %0, t; }" : "=r"(a) : "l"(p));
    return a;
}
static __device__ __forceinline__ uint32_t swz128(uint32_t off) {
    return off ^ ((off >> 3) & 0x70);
}
// pack two fp32 -> fp16x2 word: low half = a, high half = b
static __device__ __forceinline__ uint32_t cvt_f16x2(float a, float b) {
    uint32_t r;
    asm("cvt.rn.f16x2.f32 %0, %1, %2;" : "=r"(r) : "f"(b), "f"(a));
    return r;
}
static __device__ __forceinline__ void ldsm_x4(uint32_t* r, uint32_t addr) {
    asm volatile("ldmatrix.sync.aligned.m8n8.x4.shared.b16 {%0,%1,%2,%3}, [%4];"
                 : "=r"(r[0]), "=r"(r[1]), "=r"(r[2]), "=r"(r[3]) : "r"(addr));
}
static __device__ __forceinline__ void mma_f16(float* d, const uint32_t* a,
                                               uint32_t b0, uint32_t b1) {
    asm volatile("mma.sync.aligned.m16n8k16.row.col.f32.f16.f16.f32 "
                 "{%0,%1,%2,%3}, {%4,%5,%6,%7}, {%8,%9}, {%0,%1,%2,%3};"
                 : "+f"(d[0]), "+f"(d[1]), "+f"(d[2]), "+f"(d[3])
                 : "r"(a[0]), "r"(a[1]), "r"(a[2]), "r"(a[3]), "r"(b0), "r"(b1));
}

__global__ void __launch_bounds__(THREADS_, 1)
wct_mma_kernel(const float* __restrict__ x, const float* __restrict__ coords,
               const float* __restrict__ sigma, const float* __restrict__ weight,
               float* __restrict__ out) {
    extern __shared__ char smem[];
    const uint32_t sb = smem_u32(smem);
    const int tid  = threadIdx.x;
    const int wid  = tid >> 5;
    const int lane = tid & 31;

    float* x_s  = (float*)(smem + OFF_X);
    float* cs_s = (float*)(smem + OFF_CS);
    float* we_s = (float*)(smem + OFF_WE);

    // ---- one-time W (single fp16): chunk j = W[o][c] for tap j, SW128 rows ----
    for (int idx = tid; idx < 64 * 64 * 9; idx += THREADS_) {
        int j  = idx % 9;
        int oc = idx / 9;                    // oc = o*64 + c
        int c  = oc & 63;
        int o  = oc >> 6;
        __half h = __float2half_rn(weight[oc * 9 + j]);
        uint32_t bo = swz128((uint32_t)o * 128 + (uint32_t)c * 2);
        *(__half*)(smem + WCH_(j) + bo) = h;
    }
    const float rsig = 1.0f / sigma[0];

    // warp tile: 16 warps = 8 p-groups x 2 o-groups; each 16p x 32o
    const int pg = wid >> 1, og = wid & 1;
    const int pbase = pg * 16;
    const uint32_t a_ro = (uint32_t)(pbase + (lane & 15)) * 128 + (uint32_t)(lane >> 4) * 16;
    const uint32_t b_ro0 = (uint32_t)(og * 32 + 0  + (lane & 15)) * 128 + (uint32_t)(lane >> 4) * 16;
    const uint32_t b_ro1 = (uint32_t)(og * 32 + 16 + (lane & 15)) * 128 + (uint32_t)(lane >> 4) * 16;
    const int bp  = wid * 8 + (lane >> 2);
    const int bc0 = lane & 3;

    __syncthreads();  // W ready

    for (int ti = blockIdx.x; ti < TILES_; ti += gridDim.x) {
        const int b  = ti >> 7;
        const int p0 = (ti & 127) * PT_;

        // ---- phase 1: stage x (fp32) + coords, coalesced ----
        for (int idx = tid; idx < 132 * 64; idx += THREADS_) {
            int c  = idx / 132;
            int xi = idx - c * 132;
            int g  = p0 - 2 + xi;
            x_s[xi * XP_ + c] =
                ((unsigned)g < (unsigned)NIN_) ? x[((size_t)b * 64 + c) * NIN_ + g] : 0.0f;
        }
        for (int idx = tid; idx < 3 * CSP_; idx += THREADS_) {
            int d = idx / CSP_;
            int k = idx - d * CSP_;
            int g = 2 * p0 - 4 + k;
            cs_s[idx] = ((unsigned)g < (unsigned)LOUT_)
                      ? coords[((size_t)b * 3 + d) * LOUT_ + g] : 0.0f;
        }
        __syncthreads();

        // ---- phase 2: convert x -> XH/XL fp16 (SW128 rows), compute we ----
        {
            const float* xr = x_s + bp * XP_;
            const uint32_t m = ((uint32_t)bp & 7) << 4;
            char* hbase = smem + OFF_XHI + bp * 128;
            char* lbase = smem + OFF_XLO + bp * 128;
            #pragma unroll
            for (int rr = 0; rr < 4; ++rr) {
                int fo = bc0 * 4 + rr * 16;
                float2 v01 = *(const float2*)(xr + fo);
                float2 v23 = *(const float2*)(xr + fo + 2);
                uint32_t h0 = cvt_f16x2(v01.x, v01.y);
                uint32_t h1 = cvt_f16x2(v23.x, v23.y);
                __half2 h0h = *(__half2*)&h0;
                __half2 h1h = *(__half2*)&h1;
                uint32_t l0 = cvt_f16x2(v01.x - __low2float(h0h), v01.y - __high2float(h0h));
                uint32_t l1 = cvt_f16x2(v23.x - __low2float(h1h), v23.y - __high2float(h1h));
                uint32_t d = ((uint32_t)fo * 2) ^ m;
                *(uint2*)(hbase + d) = make_uint2(h0, h1);
                *(uint2*)(lbase + d) = make_uint2(l0, l1);
            }
            if (tid < 64) {                            // tail rows 128..131
                int row = 128 + (tid >> 4);
                int fo  = (tid & 15) * 4;
                const float* xr2 = x_s + row * XP_;
                const uint32_t m2 = ((uint32_t)row & 7) << 4;
                float2 v01 = *(const float2*)(xr2 + fo);
                float2 v23 = *(const float2*)(xr2 + fo + 2);
                uint32_t h0 = cvt_f16x2(v01.x, v01.y);
                uint32_t h1 = cvt_f16x2(v23.x, v23.y);
                __half2 h0h = *(__half2*)&h0;
                __half2 h1h = *(__half2*)&h1;
                uint32_t l0 = cvt_f16x2(v01.x - __low2float(h0h), v01.y - __high2float(h0h));
                uint32_t l1 = cvt_f16x2(v23.x - __low2float(h1h), v23.y - __high2float(h1h));
                uint32_t d = ((uint32_t)fo * 2) ^ m2;
                *(uint2*)(smem + OFF_XHI + row * 128 + d) = make_uint2(h0, h1);
                *(uint2*)(smem + OFF_XLO + row * 128 + d) = make_uint2(l0, l1);
            }
        }
        // radial weights we[j][p] for l = 2p + (j&1)
        for (int idx = tid; idx < 9 * 128; idx += THREADS_) {
            int j = idx >> 7;
            int p = idx & 127;
            int par = j & 1;
            int kt = 2 * p + par + j;
            int kc = 2 * p + par + 4;
            float dx = cs_s[kt] - cs_s[kc];
            float dy = cs_s[CSP_ + kt] - cs_s[CSP_ + kc];
            float dz = cs_s[2 * CSP_ + kt] - cs_s[2 * CSP_ + kc];
            float nn = sqrtf(fmaf(dx, dx, fmaf(dy, dy, dz * dz)));
            we_s[idx] = fmaxf(1.0f - nn * rsig, 0.0f);
        }
        __syncthreads();

        // ---- phase 3: toff loop (A-frags shared by the 2 taps per offset) ----
        float acc_e[16], acc_o[16];
        #pragma unroll
        for (int i = 0; i < 16; ++i) { acc_e[i] = 0.0f; acc_o[i] = 0.0f; }

        const uint32_t xhi_b = sb + OFF_XHI;
        const uint32_t xlo_b = sb + OFF_XLO;
        const int prow = pbase + (lane >> 2);

        #pragma unroll 1
        for (int toff = 0; toff < 5; ++toff) {
            const uint32_t aro = a_ro + (uint32_t)toff * 128;
            uint32_t AH[4][4], AL[4][4];
            #pragma unroll
            for (int k16 = 0; k16 < 4; ++k16) {
                const uint32_t kb = (uint32_t)k16 * 32;
                ldsm_x4(AH[k16], xhi_b + swz128(aro + kb));
                ldsm_x4(AL[k16], xlo_b + swz128(aro + kb));
            }
            #pragma unroll
            for (int s = 0; s < 2; ++s) {
                const int j = 2 * toff - 1 + s;   // s=0: odd tap, s=1: even tap
                if (j < 0) continue;
                const uint32_t wch = sb + (uint32_t)WCH_(j);

                float tmp[16];
                #pragma unroll
                for (int i = 0; i < 16; ++i) tmp[i] = 0.0f;

                #pragma unroll
                for (int k16 = 0; k16 < 4; ++k16) {
                    const uint32_t kb = (uint32_t)k16 * 32;
                    uint32_t r0[4], r1[4];
                    ldsm_x4(r0, wch + swz128(b_ro0 + kb));
                    ldsm_x4(r1, wch + swz128(b_ro1 + kb));
                    mma_f16(tmp + 0,  AH[k16], r0[0], r0[2]);
                    mma_f16(tmp + 4,  AH[k16], r0[1], r0[3]);
                    mma_f16(tmp + 8,  AH[k16], r1[0], r1[2]);
                    mma_f16(tmp + 12, AH[k16], r1[1], r1[3]);
                    mma_f16(tmp + 0,  AL[k16], r0[0], r0[2]);
                    mma_f16(tmp + 4,  AL[k16], r0[1], r0[3]);
                    mma_f16(tmp + 8,  AL[k16], r1[0], r1[2]);
                    mma_f16(tmp + 12, AL[k16], r1[1], r1[3]);
                }
                const float w0 = we_s[j * 128 + prow];
                const float w1 = we_s[j * 128 + prow + 8];
                float* acc = (j & 1) ? acc_o : acc_e;
                #pragma unroll
                for (int i = 0; i < 16; ++i) {
                    const float w = (i & 2) ? w1 : w0;
                    acc[i] = fmaf(w, tmp[i], acc[i]);
                }
            }
        }

        // ---- epilogue: float2 (even, odd) per (o, p) ----
        {
            float* obB = out + (size_t)b * 64 * LOUT_;
            #pragma unroll
            for (int jn = 0; jn < 4; ++jn) {
                #pragma unroll
                for (int e = 0; e < 2; ++e) {
                    int o = og * 32 + jn * 8 + (lane & 3) * 2 + e;
                    float* orow = obB + (size_t)o * LOUT_;
                    *(float2*)(orow + 2 * (size_t)(p0 + prow)) =
                        make_float2(acc_e[4 * jn + e], acc_o[4 * jn + e]);
                    *(float2*)(orow + 2 * (size_t)(p0 + prow + 8)) =
                        make_float2(acc_e[4 * jn + 2 + e], acc_o[4 * jn + 2 + e]);
                }
            }
        }
        __syncthreads();  // x_s / XH / we_s reuse next tile
    }
}

extern "C" void kernel_launch(void* const* d_in, const int* in_sizes, int n_in,
                              void* d_out, int out_size) {
    const float* x      = (const float*)d_in[0];
    const float* coords = (const float*)d_in[1];
    const float* sigma  = (const float*)d_in[2];
    const float* weight = (const float*)d_in[3];
    float* out = (float*)d_out;
    (void)in_sizes; (void)n_in; (void)out_size;

    cudaFuncSetAttribute(wct_mma_kernel, cudaFuncAttributeMaxDynamicSharedMemorySize, SMEM_BYTES);

    int dev = 0, sms = 148;
    cudaGetDevice(&dev);
    cudaDeviceGetAttribute(&sms, cudaDevAttrMultiProcessorCount, dev);
    if (sms <= 0) sms = 148;

    wct_mma_kernel<<<sms, THREADS_, SMEM_BYTES>>>(x, coords, sigma, weight, out);
}

// round 9
// speedup vs baseline: 1.3521x; 1.3521x over previous
#include <cuda_runtime.h>
#include <cuda_fp16.h>
#include <cstdint>

// WeightedConvTranspose via mma.sync (fp16 m16n8k16, fp32 accum), parity-decomposed.
// R9 = R7 loop structure (low reg pressure) + 2-product fp16 scheme:
//   x split into fp16 hi+lo (captures ~22 mantissa bits), W single fp16.
//   (x_h + x_l) * w_h : 2 MMAs per (tap, k16) instead of 3; B plane halved.
// Radial weight we[j,p] applied in fp32 on the per-tap accumulator.
// NO A-fragment caching across taps (R8 showed that hits the 128-reg RF cap).

#define B_       8
#define NIN_     16384
#define LOUT_    32768
#define PT_      128
#define THREADS_ 512
#define TILES_   (B_ * (NIN_ / PT_))   // 1024

#define XP_      66
#define CSP_     264

// ---- SMEM layout (bytes) ----
#define OFF_W    0                      // 9 chunks x 8192 (fp16 W) = 73728
#define WCH_(j)  (OFF_W + (j) * 8192)
#define OFF_XHI  73728                  // 132 rows x 128B = 16896
#define OFF_XLO  (OFF_XHI + 16896)      // 90624
#define OFF_X    (OFF_XLO + 16896)      // 107520: fp32 stage 132*66*4 = 34848
#define OFF_CS   (OFF_X + 34848)        // 142368: 3*264*4 = 3168
#define OFF_WE   (OFF_CS + 3168)        // 145536: 9*128*4 = 4608
#define SMEM_BYTES (OFF_WE + 4608)      // 150144

static __device__ __forceinline__ uint32_t smem_u32(const void* p) {
    uint32_t a;
    asm("{ .reg .u64 t; cvta.to.shared.u64 t, %1; cvt.u32.u64 %0, t; }" : "=r"(a) : "l"(p));
    return a;
}
static __device__ __forceinline__ uint32_t swz128(uint32_t off) {
    return off ^ ((off >> 3) & 0x70);
}
// pack two fp32 -> fp16x2 word: low half = a, high half = b
static __device__ __forceinline__ uint32_t cvt_f16x2(float a, float b) {
    uint32_t r;
    asm("cvt.rn.f16x2.f32 %0, %1, %2;" : "=r"(r) : "f"(b), "f"(a));
    return r;
}
static __device__ __forceinline__ void ldsm_x4(uint32_t* r, uint32_t addr) {
    asm volatile("ldmatrix.sync.aligned.m8n8.x4.shared.b16 {%0,%1,%2,%3}, [%4];"
                 : "=r"(r[0]), "=r"(r[1]), "=r"(r[2]), "=r"(r[3]) : "r"(addr));
}
static __device__ __forceinline__ void mma_f16(float* d, const uint32_t* a,
                                               uint32_t b0, uint32_t b1) {
    asm volatile("mma.sync.aligned.m16n8k16.row.col.f32.f16.f16.f32 "
                 "{%0,%1,%2,%3}, {%4,%5,%6,%7}, {%8,%9}, {%0,%1,%2,%3};"
                 : "+f"(d[0]), "+f"(d[1]), "+f"(d[2]), "+f"(d[3])
                 : "r"(a[0]), "r"(a[1]), "r"(a[2]), "r"(a[3]), "r"(b0), "r"(b1));
}

__global__ void __launch_bounds__(THREADS_, 1)
wct_mma_kernel(const float* __restrict__ x, const float* __restrict__ coords,
               const float* __restrict__ sigma, const float* __restrict__ weight,
               float* __restrict__ out) {
    extern __shared__ char smem[];
    const uint32_t sb = smem_u32(smem);
    const int tid  = threadIdx.x;
    const int wid  = tid >> 5;
    const int lane = tid & 31;

    float* x_s  = (float*)(smem + OFF_X);
    float* cs_s = (float*)(smem + OFF_CS);
    float* we_s = (float*)(smem + OFF_WE);

    // ---- one-time W (single fp16): chunk j = W[o][c] for tap j, SW128 rows ----
    for (int idx = tid; idx < 64 * 64 * 9; idx += THREADS_) {
        int j  = idx % 9;
        int oc = idx / 9;                    // oc = o*64 + c
        int c  = oc & 63;
        int o  = oc >> 6;
        __half h = __float2half_rn(weight[oc * 9 + j]);
        uint32_t bo = swz128((uint32_t)o * 128 + (uint32_t)c * 2);
        *(__half*)(smem + WCH_(j) + bo) = h;
    }
    const float rsig = 1.0f / sigma[0];

    // warp tile: 16 warps = 8 p-groups x 2 o-groups; each 16p x 32o
    const int pg = wid >> 1, og = wid & 1;
    const int pbase = pg * 16;
    const uint32_t a_ro = (uint32_t)(pbase + (lane & 15)) * 128 + (uint32_t)(lane >> 4) * 16;
    const uint32_t b_ro0 = (uint32_t)(og * 32 + 0  + (lane & 15)) * 128 + (uint32_t)(lane >> 4) * 16;
    const uint32_t b_ro1 = (uint32_t)(og * 32 + 16 + (lane & 15)) * 128 + (uint32_t)(lane >> 4) * 16;
    const int bp  = wid * 8 + (lane >> 2);
    const int bc0 = lane & 3;

    __syncthreads();  // W ready

    for (int ti = blockIdx.x; ti < TILES_; ti += gridDim.x) {
        const int b  = ti >> 7;
        const int p0 = (ti & 127) * PT_;

        // ---- phase 1: stage x (fp32) + coords, coalesced ----
        for (int idx = tid; idx < 132 * 64; idx += THREADS_) {
            int c  = idx / 132;
            int xi = idx - c * 132;
            int g  = p0 - 2 + xi;
            x_s[xi * XP_ + c] =
                ((unsigned)g < (unsigned)NIN_) ? x[((size_t)b * 64 + c) * NIN_ + g] : 0.0f;
        }
        for (int idx = tid; idx < 3 * CSP_; idx += THREADS_) {
            int d = idx / CSP_;
            int k = idx - d * CSP_;
            int g = 2 * p0 - 4 + k;
            cs_s[idx] = ((unsigned)g < (unsigned)LOUT_)
                      ? coords[((size_t)b * 3 + d) * LOUT_ + g] : 0.0f;
        }
        __syncthreads();

        // ---- phase 2: convert x -> XH/XL fp16 (SW128 rows), compute we ----
        {
            const float* xr = x_s + bp * XP_;
            const uint32_t m = ((uint32_t)bp & 7) << 4;
            char* hbase = smem + OFF_XHI + bp * 128;
            char* lbase = smem + OFF_XLO + bp * 128;
            #pragma unroll
            for (int rr = 0; rr < 4; ++rr) {
                int fo = bc0 * 4 + rr * 16;
                float2 v01 = *(const float2*)(xr + fo);
                float2 v23 = *(const float2*)(xr + fo + 2);
                uint32_t h0 = cvt_f16x2(v01.x, v01.y);
                uint32_t h1 = cvt_f16x2(v23.x, v23.y);
                __half2 h0h = *(__half2*)&h0;
                __half2 h1h = *(__half2*)&h1;
                uint32_t l0 = cvt_f16x2(v01.x - __low2float(h0h), v01.y - __high2float(h0h));
                uint32_t l1 = cvt_f16x2(v23.x - __low2float(h1h), v23.y - __high2float(h1h));
                uint32_t d = ((uint32_t)fo * 2) ^ m;
                *(uint2*)(hbase + d) = make_uint2(h0, h1);
                *(uint2*)(lbase + d) = make_uint2(l0, l1);
            }
            if (tid < 64) {                            // tail rows 128..131
                int row = 128 + (tid >> 4);
                int fo  = (tid & 15) * 4;
                const float* xr2 = x_s + row * XP_;
                const uint32_t m2 = ((uint32_t)row & 7) << 4;
                float2 v01 = *(const float2*)(xr2 + fo);
                float2 v23 = *(const float2*)(xr2 + fo + 2);
                uint32_t h0 = cvt_f16x2(v01.x, v01.y);
                uint32_t h1 = cvt_f16x2(v23.x, v23.y);
                __half2 h0h = *(__half2*)&h0;
                __half2 h1h = *(__half2*)&h1;
                uint32_t l0 = cvt_f16x2(v01.x - __low2float(h0h), v01.y - __high2float(h0h));
                uint32_t l1 = cvt_f16x2(v23.x - __low2float(h1h), v23.y - __high2float(h1h));
                uint32_t d = ((uint32_t)fo * 2) ^ m2;
                *(uint2*)(smem + OFF_XHI + row * 128 + d) = make_uint2(h0, h1);
                *(uint2*)(smem + OFF_XLO + row * 128 + d) = make_uint2(l0, l1);
            }
        }
        // radial weights we[j][p] for l = 2p + (j&1)
        for (int idx = tid; idx < 9 * 128; idx += THREADS_) {
            int j = idx >> 7;
            int p = idx & 127;
            int par = j & 1;
            int kt = 2 * p + par + j;
            int kc = 2 * p + par + 4;
            float dx = cs_s[kt] - cs_s[kc];
            float dy = cs_s[CSP_ + kt] - cs_s[CSP_ + kc];
            float dz = cs_s[2 * CSP_ + kt] - cs_s[2 * CSP_ + kc];
            float nn = sqrtf(fmaf(dx, dx, fmaf(dy, dy, dz * dz)));
            we_s[idx] = fmaxf(1.0f - nn * rsig, 0.0f);
        }
        __syncthreads();

        // ---- phase 3: chunk loop (R7 structure), sync-free ----
        float acc_e[16], acc_o[16];
        #pragma unroll
        for (int i = 0; i < 16; ++i) { acc_e[i] = 0.0f; acc_o[i] = 0.0f; }

        const uint32_t xhi_b = sb + OFF_XHI;
        const uint32_t xlo_b = sb + OFF_XLO;
        const int prow = pbase + (lane >> 2);

        #pragma unroll 1
        for (int j = 0; j < 9; ++j) {
            const int toff = (j >> 1) + (j & 1);
            const uint32_t wch = sb + (uint32_t)WCH_(j);
            const uint32_t aro = a_ro + (uint32_t)toff * 128;

            float tmp[16];
            #pragma unroll
            for (int i = 0; i < 16; ++i) tmp[i] = 0.0f;

            #pragma unroll
            for (int k16 = 0; k16 < 4; ++k16) {
                const uint32_t kb = (uint32_t)k16 * 32;
                uint32_t ah[4], al[4];
                ldsm_x4(ah, xhi_b + swz128(aro + kb));
                ldsm_x4(al, xlo_b + swz128(aro + kb));
                uint32_t r0[4], r1[4];
                ldsm_x4(r0, wch + swz128(b_ro0 + kb));
                ldsm_x4(r1, wch + swz128(b_ro1 + kb));
                mma_f16(tmp + 0,  ah, r0[0], r0[2]);
                mma_f16(tmp + 4,  ah, r0[1], r0[3]);
                mma_f16(tmp + 8,  ah, r1[0], r1[2]);
                mma_f16(tmp + 12, ah, r1[1], r1[3]);
                mma_f16(tmp + 0,  al, r0[0], r0[2]);
                mma_f16(tmp + 4,  al, r0[1], r0[3]);
                mma_f16(tmp + 8,  al, r1[0], r1[2]);
                mma_f16(tmp + 12, al, r1[1], r1[3]);
            }
            // scale by we[j, prow(+8)] and accumulate
            const float w0 = we_s[j * 128 + prow];
            const float w1 = we_s[j * 128 + prow + 8];
            float* acc = (j & 1) ? acc_o : acc_e;
            #pragma unroll
            for (int i = 0; i < 16; ++i) {
                const float w = (i & 2) ? w1 : w0;
                acc[i] = fmaf(w, tmp[i], acc[i]);
            }
        }

        // ---- epilogue: float2 (even, odd) per (o, p) ----
        {
            float* obB = out + (size_t)b * 64 * LOUT_;
            #pragma unroll
            for (int jn = 0; jn < 4; ++jn) {
                #pragma unroll
                for (int e = 0; e < 2; ++e) {
                    int o = og * 32 + jn * 8 + (lane & 3) * 2 + e;
                    float* orow = obB + (size_t)o * LOUT_;
                    *(float2*)(orow + 2 * (size_t)(p0 + prow)) =
                        make_float2(acc_e[4 * jn + e], acc_o[4 * jn + e]);
                    *(float2*)(orow + 2 * (size_t)(p0 + prow + 8)) =
                        make_float2(acc_e[4 * jn + 2 + e], acc_o[4 * jn + 2 + e]);
                }
            }
        }
        __syncthreads();  // x_s / XH / we_s reuse next tile
    }
}

extern "C" void kernel_launch(void* const* d_in, const int* in_sizes, int n_in,
                              void* d_out, int out_size) {
    const float* x      = (const float*)d_in[0];
    const float* coords = (const float*)d_in[1];
    const float* sigma  = (const float*)d_in[2];
    const float* weight = (const float*)d_in[3];
    float* out = (float*)d_out;
    (void)in_sizes; (void)n_in; (void)out_size;

    cudaFuncSetAttribute(wct_mma_kernel, cudaFuncAttributeMaxDynamicSharedMemorySize, SMEM_BYTES);

    int dev = 0, sms = 148;
    cudaGetDevice(&dev);
    cudaDeviceGetAttribute(&sms, cudaDevAttrMultiProcessorCount, dev);
    if (sms <= 0) sms = 148;

    wct_mma_kernel<<<sms, THREADS_, SMEM_BYTES>>>(x, coords, sigma, weight, out);
}

// round 10
// speedup vs baseline: 1.6748x; 1.2386x over previous
#include <cuda_runtime.h>
#include <cuda_fp16.h>
#include <cstdint>

// WeightedConvTranspose via mma.sync (fp16 m16n8k16, fp32 accum), parity-decomposed.
// R10 = R9 structure with single-product fp16: x_h * w_h only.
//   Error budget: W fp16 rounding ~2.1e-4 (measured R9) + x fp16 rounding ~2.8e-4 RMS
//   -> ~3.5e-4 expected, threshold 1e-3.
// Radial weight we[j,p] applied in fp32 on the per-tap accumulator.

#define B_       8
#define NIN_     16384
#define LOUT_    32768
#define PT_      128
#define THREADS_ 512
#define TILES_   (B_ * (NIN_ / PT_))   // 1024

#define XP_      66
#define CSP_     264

// ---- SMEM layout (bytes) ----
#define OFF_W    0                      // 9 chunks x 8192 (fp16 W) = 73728
#define WCH_(j)  (OFF_W + (j) * 8192)
#define OFF_XHI  73728                  // 132 rows x 128B = 16896
#define OFF_X    90624                  // fp32 stage 132*66*4 = 34848
#define OFF_CS   125472                 // 3*264*4 = 3168
#define OFF_WE   128640                 // 9*128*4 = 4608
#define SMEM_BYTES 133248

static __device__ __forceinline__ uint32_t smem_u32(const void* p) {
    uint32_t a;
    asm("{ .reg .u64 t; cvta.to.shared.u64 t, %1; cvt.u32.u64 %0, t; }" : "=r"(a) : "l"(p));
    return a;
}
static __device__ __forceinline__ uint32_t swz128(uint32_t off) {
    return off ^ ((off >> 3) & 0x70);
}
// pack two fp32 -> fp16x2 word: low half = a, high half = b
static __device__ __forceinline__ uint32_t cvt_f16x2(float a, float b) {
    uint32_t r;
    asm("cvt.rn.f16x2.f32 %0, %1, %2;" : "=r"(r) : "f"(b), "f"(a));
    return r;
}
static __device__ __forceinline__ void ldsm_x4(uint32_t* r, uint32_t addr) {
    asm volatile("ldmatrix.sync.aligned.m8n8.x4.shared.b16 {%0,%1,%2,%3}, [%4];"
                 : "=r"(r[0]), "=r"(r[1]), "=r"(r[2]), "=r"(r[3]) : "r"(addr));
}
static __device__ __forceinline__ void mma_f16(float* d, const uint32_t* a,
                                               uint32_t b0, uint32_t b1) {
    asm volatile("mma.sync.aligned.m16n8k16.row.col.f32.f16.f16.f32 "
                 "{%0,%1,%2,%3}, {%4,%5,%6,%7}, {%8,%9}, {%0,%1,%2,%3};"
                 : "+f"(d[0]), "+f"(d[1]), "+f"(d[2]), "+f"(d[3])
                 : "r"(a[0]), "r"(a[1]), "r"(a[2]), "r"(a[3]), "r"(b0), "r"(b1));
}

__global__ void __launch_bounds__(THREADS_, 1)
wct_mma_kernel(const float* __restrict__ x, const float* __restrict__ coords,
               const float* __restrict__ sigma, const float* __restrict__ weight,
               float* __restrict__ out) {
    extern __shared__ char smem[];
    const uint32_t sb = smem_u32(smem);
    const int tid  = threadIdx.x;
    const int wid  = tid >> 5;
    const int lane = tid & 31;

    float* x_s  = (float*)(smem + OFF_X);
    float* cs_s = (float*)(smem + OFF_CS);
    float* we_s = (float*)(smem + OFF_WE);

    // ---- one-time W (single fp16): chunk j = W[o][c] for tap j, SW128 rows ----
    for (int idx = tid; idx < 64 * 64 * 9; idx += THREADS_) {
        int j  = idx % 9;
        int oc = idx / 9;                    // oc = o*64 + c
        int c  = oc & 63;
        int o  = oc >> 6;
        __half h = __float2half_rn(weight[oc * 9 + j]);
        uint32_t bo = swz128((uint32_t)o * 128 + (uint32_t)c * 2);
        *(__half*)(smem + WCH_(j) + bo) = h;
    }
    const float rsig = 1.0f / sigma[0];

    // warp tile: 16 warps = 8 p-groups x 2 o-groups; each 16p x 32o
    const int pg = wid >> 1, og = wid & 1;
    const int pbase = pg * 16;
    const uint32_t a_ro = (uint32_t)(pbase + (lane & 15)) * 128 + (uint32_t)(lane >> 4) * 16;
    const uint32_t b_ro0 = (uint32_t)(og * 32 + 0  + (lane & 15)) * 128 + (uint32_t)(lane >> 4) * 16;
    const uint32_t b_ro1 = (uint32_t)(og * 32 + 16 + (lane & 15)) * 128 + (uint32_t)(lane >> 4) * 16;
    const int bp  = wid * 8 + (lane >> 2);
    const int bc0 = lane & 3;

    __syncthreads();  // W ready

    for (int ti = blockIdx.x; ti < TILES_; ti += gridDim.x) {
        const int b  = ti >> 7;
        const int p0 = (ti & 127) * PT_;

        // ---- phase 1: stage x (fp32) + coords, coalesced ----
        for (int idx = tid; idx < 132 * 64; idx += THREADS_) {
            int c  = idx / 132;
            int xi = idx - c * 132;
            int g  = p0 - 2 + xi;
            x_s[xi * XP_ + c] =
                ((unsigned)g < (unsigned)NIN_) ? x[((size_t)b * 64 + c) * NIN_ + g] : 0.0f;
        }
        for (int idx = tid; idx < 3 * CSP_; idx += THREADS_) {
            int d = idx / CSP_;
            int k = idx - d * CSP_;
            int g = 2 * p0 - 4 + k;
            cs_s[idx] = ((unsigned)g < (unsigned)LOUT_)
                      ? coords[((size_t)b * 3 + d) * LOUT_ + g] : 0.0f;
        }
        __syncthreads();

        // ---- phase 2: convert x -> XH fp16 (SW128 rows), compute we ----
        {
            const float* xr = x_s + bp * XP_;
            const uint32_t m = ((uint32_t)bp & 7) << 4;
            char* hbase = smem + OFF_XHI + bp * 128;
            #pragma unroll
            for (int rr = 0; rr < 4; ++rr) {
                int fo = bc0 * 4 + rr * 16;
                float2 v01 = *(const float2*)(xr + fo);
                float2 v23 = *(const float2*)(xr + fo + 2);
                uint32_t h0 = cvt_f16x2(v01.x, v01.y);
                uint32_t h1 = cvt_f16x2(v23.x, v23.y);
                uint32_t d = ((uint32_t)fo * 2) ^ m;
                *(uint2*)(hbase + d) = make_uint2(h0, h1);
            }
            if (tid < 64) {                            // tail rows 128..131
                int row = 128 + (tid >> 4);
                int fo  = (tid & 15) * 4;
                const float* xr2 = x_s + row * XP_;
                const uint32_t m2 = ((uint32_t)row & 7) << 4;
                float2 v01 = *(const float2*)(xr2 + fo);
                float2 v23 = *(const float2*)(xr2 + fo + 2);
                uint32_t h0 = cvt_f16x2(v01.x, v01.y);
                uint32_t h1 = cvt_f16x2(v23.x, v23.y);
                uint32_t d = ((uint32_t)fo * 2) ^ m2;
                *(uint2*)(smem + OFF_XHI + row * 128 + d) = make_uint2(h0, h1);
            }
        }
        // radial weights we[j][p] for l = 2p + (j&1)
        for (int idx = tid; idx < 9 * 128; idx += THREADS_) {
            int j = idx >> 7;
            int p = idx & 127;
            int par = j & 1;
            int kt = 2 * p + par + j;
            int kc = 2 * p + par + 4;
            float dx = cs_s[kt] - cs_s[kc];
            float dy = cs_s[CSP_ + kt] - cs_s[CSP_ + kc];
            float dz = cs_s[2 * CSP_ + kt] - cs_s[2 * CSP_ + kc];
            float nn = sqrtf(fmaf(dx, dx, fmaf(dy, dy, dz * dz)));
            we_s[idx] = fmaxf(1.0f - nn * rsig, 0.0f);
        }
        __syncthreads();

        // ---- phase 3: chunk loop, sync-free ----
        float acc_e[16], acc_o[16];
        #pragma unroll
        for (int i = 0; i < 16; ++i) { acc_e[i] = 0.0f; acc_o[i] = 0.0f; }

        const uint32_t xhi_b = sb + OFF_XHI;
        const int prow = pbase + (lane >> 2);

        #pragma unroll 1
        for (int j = 0; j < 9; ++j) {
            const int toff = (j >> 1) + (j & 1);
            const uint32_t wch = sb + (uint32_t)WCH_(j);
            const uint32_t aro = a_ro + (uint32_t)toff * 128;

            float tmp[16];
            #pragma unroll
            for (int i = 0; i < 16; ++i) tmp[i] = 0.0f;

            #pragma unroll
            for (int k16 = 0; k16 < 4; ++k16) {
                const uint32_t kb = (uint32_t)k16 * 32;
                uint32_t ah[4];
                ldsm_x4(ah, xhi_b + swz128(aro + kb));
                uint32_t r0[4], r1[4];
                ldsm_x4(r0, wch + swz128(b_ro0 + kb));
                ldsm_x4(r1, wch + swz128(b_ro1 + kb));
                mma_f16(tmp + 0,  ah, r0[0], r0[2]);
                mma_f16(tmp + 4,  ah, r0[1], r0[3]);
                mma_f16(tmp + 8,  ah, r1[0], r1[2]);
                mma_f16(tmp + 12, ah, r1[1], r1[3]);
            }
            // scale by we[j, prow(+8)] and accumulate
            const float w0 = we_s[j * 128 + prow];
            const float w1 = we_s[j * 128 + prow + 8];
            float* acc = (j & 1) ? acc_o : acc_e;
            #pragma unroll
            for (int i = 0; i < 16; ++i) {
                const float w = (i & 2) ? w1 : w0;
                acc[i] = fmaf(w, tmp[i], acc[i]);
            }
        }

        // ---- epilogue: float2 (even, odd) per (o, p) ----
        {
            float* obB = out + (size_t)b * 64 * LOUT_;
            #pragma unroll
            for (int jn = 0; jn < 4; ++jn) {
                #pragma unroll
                for (int e = 0; e < 2; ++e) {
                    int o = og * 32 + jn * 8 + (lane & 3) * 2 + e;
                    float* orow = obB + (size_t)o * LOUT_;
                    *(float2*)(orow + 2 * (size_t)(p0 + prow)) =
                        make_float2(acc_e[4 * jn + e], acc_o[4 * jn + e]);
                    *(float2*)(orow + 2 * (size_t)(p0 + prow + 8)) =
                        make_float2(acc_e[4 * jn + 2 + e], acc_o[4 * jn + 2 + e]);
                }
            }
        }
        __syncthreads();  // x_s / XH / we_s reuse next tile
    }
}

extern "C" void kernel_launch(void* const* d_in, const int* in_sizes, int n_in,
                              void* d_out, int out_size) {
    const float* x      = (const float*)d_in[0];
    const float* coords = (const float*)d_in[1];
    const float* sigma  = (const float*)d_in[2];
    const float* weight = (const float*)d_in[3];
    float* out = (float*)d_out;
    (void)in_sizes; (void)n_in; (void)out_size;

    cudaFuncSetAttribute(wct_mma_kernel, cudaFuncAttributeMaxDynamicSharedMemorySize, SMEM_BYTES);

    int dev = 0, sms = 148;
    cudaGetDevice(&dev);
    cudaDeviceGetAttribute(&sms, cudaDevAttrMultiProcessorCount, dev);
    if (sms <= 0) sms = 148;

    wct_mma_kernel<<<sms, THREADS_, SMEM_BYTES>>>(x, coords, sigma, weight, out);
}

// round 11
// speedup vs baseline: 2.2078x; 1.3183x over previous
#include <cuda_runtime.h>
#include <cuda_fp16.h>
#include <cstdint>

// WeightedConvTranspose via mma.sync (fp16 m16n8k16, fp32 accum), parity-decomposed.
// R11 = R10 + cp.async double-buffered staging pipeline:
//   x/coords for tile i+1 stream in (LDGSTS) while tile i runs MMA.
//   x staged as [c][xi] (pitch 132 floats, 8B cp.async chunks since p0-2 is 8B-aligned);
//   phase-2 transposes during the fp16 convert (2-way LDS conflicts).
// Single-product fp16 (x_h * w_h), we[j,p] applied in fp32 on the accumulator.

#define B_       8
#define NIN_     16384
#define LOUT_    32768
#define PT_      128
#define THREADS_ 512
#define TILES_   (B_ * (NIN_ / PT_))   // 1024

#define XSP_     132                    // x stage pitch (floats)
#define CSP_     264

// ---- SMEM layout (bytes) ----
#define OFF_W    0                      // 9 chunks x 8192 (fp16 W) = 73728
#define WCH_(j)  (OFF_W + (j) * 8192)
#define OFF_XHI  73728                  // XH: 132 rows x 128B = 16896
#define OFF_XS   90624                  // 2 bufs x 64*132*4 = 2 x 33792
#define OFF_CSB  158208                 // 2 bufs x 3*264*4  = 2 x 3168
#define OFF_WE   164544                 // 9*128*4 = 4608
#define SMEM_BYTES 169152

static __device__ __forceinline__ uint32_t smem_u32(const void* p) {
    uint32_t a;
    asm("{ .reg .u64 t; cvta.to.shared.u64 t, %1; cvt.u32.u64 %0, t; }" : "=r"(a) : "l"(p));
    return a;
}
static __device__ __forceinline__ uint32_t swz128(uint32_t off) {
    return off ^ ((off >> 3) & 0x70);
}
static __device__ __forceinline__ uint32_t cvt_f16x2(float a, float b) {
    uint32_t r;
    asm("cvt.rn.f16x2.f32 %0, %1, %2;" : "=r"(r) : "f"(b), "f"(a));
    return r;
}
static __device__ __forceinline__ void ldsm_x4(uint32_t* r, uint32_t addr) {
    asm volatile("ldmatrix.sync.aligned.m8n8.x4.shared.b16 {%0,%1,%2,%3}, [%4];"
                 : "=r"(r[0]), "=r"(r[1]), "=r"(r[2]), "=r"(r[3]) : "r"(addr));
}
static __device__ __forceinline__ void mma_f16(float* d, const uint32_t* a,
                                               uint32_t b0, uint32_t b1) {
    asm volatile("mma.sync.aligned.m16n8k16.row.col.f32.f16.f16.f32 "
                 "{%0,%1,%2,%3}, {%4,%5,%6,%7}, {%8,%9}, {%0,%1,%2,%3};"
                 : "+f"(d[0]), "+f"(d[1]), "+f"(d[2]), "+f"(d[3])
                 : "r"(a[0]), "r"(a[1]), "r"(a[2]), "r"(a[3]), "r"(b0), "r"(b1));
}
static __device__ __forceinline__ void cp8(uint32_t dst, const float* src, int valid) {
    asm volatile("cp.async.ca.shared.global [%0], [%1], 8, %2;"
                 :: "r"(dst), "l"(src), "r"(valid) : "memory");
}
static __device__ __forceinline__ void cp16(uint32_t dst, const float* src, int valid) {
    asm volatile("cp.async.ca.shared.global [%0], [%1], 16, %2;"
                 :: "r"(dst), "l"(src), "r"(valid) : "memory");
}

__global__ void __launch_bounds__(THREADS_, 1)
wct_mma_kernel(const float* __restrict__ x, const float* __restrict__ coords,
               const float* __restrict__ sigma, const float* __restrict__ weight,
               float* __restrict__ out) {
    extern __shared__ char smem[];
    const uint32_t sb = smem_u32(smem);
    const int tid  = threadIdx.x;
    const int wid  = tid >> 5;
    const int lane = tid & 31;

    float* cs_s = nullptr;  // set per tile (buffered)
    float* we_s = (float*)(smem + OFF_WE);

    // ---- one-time W (single fp16): chunk j = W[o][c] for tap j, SW128 rows ----
    for (int idx = tid; idx < 64 * 64 * 9; idx += THREADS_) {
        int j  = idx % 9;
        int oc = idx / 9;
        int c  = oc & 63;
        int o  = oc >> 6;
        __half h = __float2half_rn(weight[oc * 9 + j]);
        uint32_t bo = swz128((uint32_t)o * 128 + (uint32_t)c * 2);
        *(__half*)(smem + WCH_(j) + bo) = h;
    }
    const float rsig = 1.0f / sigma[0];

    // warp tile mappings (as R10)
    const int pg = wid >> 1, og = wid & 1;
    const int pbase = pg * 16;
    const uint32_t a_ro = (uint32_t)(pbase + (lane & 15)) * 128 + (uint32_t)(lane >> 4) * 16;
    const uint32_t b_ro0 = (uint32_t)(og * 32 + 0  + (lane & 15)) * 128 + (uint32_t)(lane >> 4) * 16;
    const uint32_t b_ro1 = (uint32_t)(og * 32 + 16 + (lane & 15)) * 128 + (uint32_t)(lane >> 4) * 16;
    const int bp  = wid * 8 + (lane >> 2);
    const int bc0 = lane & 3;

    // ---- cp.async issue for one tile into buffer 'buf' ----
    auto issue_cp = [&](int ti, int buf) {
        const int b  = ti >> 7;
        const int p0 = (ti & 127) * PT_;
        const float* xb = x + (size_t)b * 64 * NIN_;
        const uint32_t xsd = sb + OFF_XS + (uint32_t)buf * 33792u;
        // x: 64 c-rows x 66 chunks of 2 floats; xi0 = 2*ch, g = p0-2+xi0
        for (int idx = tid; idx < 64 * 66; idx += THREADS_) {
            int c  = idx / 66;
            int ch = idx - c * 66;
            int xi0 = 2 * ch;
            int g0  = p0 - 2 + xi0;
            int gc  = g0 < 0 ? 0 : (g0 > NIN_ - 2 ? NIN_ - 2 : g0);
            int rem = NIN_ - g0;
            int valid = (g0 < 0) ? 8 : (rem >= 2 ? 8 : (rem == 1 ? 4 : 0));
            cp8(xsd + (uint32_t)(c * XSP_ + xi0) * 4u, xb + (size_t)c * NIN_ + gc, valid);
        }
        const float* cb = coords + (size_t)b * 3 * LOUT_;
        const uint32_t csd = sb + OFF_CSB + (uint32_t)buf * 3168u;
        // coords: 3 rows x 66 chunks of 4 floats; k0 = 4*ch, g = 2*p0-4+k0
        for (int idx = tid; idx < 3 * 66; idx += THREADS_) {
            int d  = idx / 66;
            int ch = idx - d * 66;
            int k0 = 4 * ch;
            int g0 = 2 * p0 - 4 + k0;
            int gc = g0 < 0 ? 0 : (g0 > LOUT_ - 4 ? LOUT_ - 4 : g0);
            int rem = LOUT_ - g0;
            int valid = (g0 < 0) ? 0 : (rem >= 4 ? 16 : (rem > 0 ? rem * 4 : 0));
            cp16(csd + (uint32_t)(d * CSP_ + k0) * 4u, cb + (size_t)d * LOUT_ + gc, valid);
        }
    };

    __syncthreads();  // W ready

    // prologue: stage first tile
    if ((int)blockIdx.x < TILES_) issue_cp(blockIdx.x, 0);
    asm volatile("cp.async.commit_group;" ::: "memory");

    int it = 0;
    for (int ti = blockIdx.x; ti < TILES_; ti += gridDim.x, ++it) {
        const int buf = it & 1;
        const int b   = ti >> 7;
        const int p0  = (ti & 127) * PT_;
        const int nxt = ti + gridDim.x;

        if (nxt < TILES_) {
            issue_cp(nxt, buf ^ 1);
            asm volatile("cp.async.commit_group;" ::: "memory");
            asm volatile("cp.async.wait_group 1;" ::: "memory");
        } else {
            asm volatile("cp.async.commit_group;" ::: "memory");
            asm volatile("cp.async.wait_group 0;" ::: "memory");
        }
        __syncthreads();  // staged data visible to all

        float* xsB = (float*)(smem + OFF_XS + (uint32_t)buf * 33792u);
        cs_s = (float*)(smem + OFF_CSB + (uint32_t)buf * 3168u);

        // left-edge fixup: xi 0,1 correspond to g = -2,-1 -> 0
        if (p0 == 0) {
            if (tid < 64) {
                float* r = xsB + tid * XSP_;
                r[0] = 0.0f; r[1] = 0.0f;
            }
            __syncthreads();
        }

        // ---- phase 2: convert x[c][xi] -> XH[xi][c] fp16 (SW128), compute we ----
        {
            const uint32_t m = ((uint32_t)bp & 7) << 4;
            char* hbase = smem + OFF_XHI + bp * 128;
            #pragma unroll
            for (int rr = 0; rr < 4; ++rr) {
                int c0 = bc0 * 4 + rr * 16;
                float a0 = xsB[(c0 + 0) * XSP_ + bp];
                float a1 = xsB[(c0 + 1) * XSP_ + bp];
                float a2 = xsB[(c0 + 2) * XSP_ + bp];
                float a3 = xsB[(c0 + 3) * XSP_ + bp];
                uint32_t h0 = cvt_f16x2(a0, a1);
                uint32_t h1 = cvt_f16x2(a2, a3);
                uint32_t d = ((uint32_t)c0 * 2) ^ m;
                *(uint2*)(hbase + d) = make_uint2(h0, h1);
            }
            if (tid < 64) {                            // tail rows 128..131
                int row = 128 + (tid >> 4);
                int c0  = (tid & 15) * 4;
                const uint32_t m2 = ((uint32_t)row & 7) << 4;
                float a0 = xsB[(c0 + 0) * XSP_ + row];
                float a1 = xsB[(c0 + 1) * XSP_ + row];
                float a2 = xsB[(c0 + 2) * XSP_ + row];
                float a3 = xsB[(c0 + 3) * XSP_ + row];
                uint32_t h0 = cvt_f16x2(a0, a1);
                uint32_t h1 = cvt_f16x2(a2, a3);
                uint32_t d = ((uint32_t)c0 * 2) ^ m2;
                *(uint2*)(smem + OFF_XHI + row * 128 + d) = make_uint2(h0, h1);
            }
        }
        // radial weights we[j][p] for l = 2p + (j&1)
        for (int idx = tid; idx < 9 * 128; idx += THREADS_) {
            int j = idx >> 7;
            int p = idx & 127;
            int par = j & 1;
            int kt = 2 * p + par + j;
            int kc = 2 * p + par + 4;
            float dx = cs_s[kt] - cs_s[kc];
            float dy = cs_s[CSP_ + kt] - cs_s[CSP_ + kc];
            float dz = cs_s[2 * CSP_ + kt] - cs_s[2 * CSP_ + kc];
            float nn = sqrtf(fmaf(dx, dx, fmaf(dy, dy, dz * dz)));
            we_s[idx] = fmaxf(1.0f - nn * rsig, 0.0f);
        }
        __syncthreads();

        // ---- phase 3: chunk loop, sync-free ----
        float acc_e[16], acc_o[16];
        #pragma unroll
        for (int i = 0; i < 16; ++i) { acc_e[i] = 0.0f; acc_o[i] = 0.0f; }

        const uint32_t xhi_b = sb + OFF_XHI;
        const int prow = pbase + (lane >> 2);

        #pragma unroll 1
        for (int j = 0; j < 9; ++j) {
            const int toff = (j >> 1) + (j & 1);
            const uint32_t wch = sb + (uint32_t)WCH_(j);
            const uint32_t aro = a_ro + (uint32_t)toff * 128;

            float tmp[16];
            #pragma unroll
            for (int i = 0; i < 16; ++i) tmp[i] = 0.0f;

            #pragma unroll
            for (int k16 = 0; k16 < 4; ++k16) {
                const uint32_t kb = (uint32_t)k16 * 32;
                uint32_t ah[4];
                ldsm_x4(ah, xhi_b + swz128(aro + kb));
                uint32_t r0[4], r1[4];
                ldsm_x4(r0, wch + swz128(b_ro0 + kb));
                ldsm_x4(r1, wch + swz128(b_ro1 + kb));
                mma_f16(tmp + 0,  ah, r0[0], r0[2]);
                mma_f16(tmp + 4,  ah, r0[1], r0[3]);
                mma_f16(tmp + 8,  ah, r1[0], r1[2]);
                mma_f16(tmp + 12, ah, r1[1], r1[3]);
            }
            const float w0 = we_s[j * 128 + prow];
            const float w1 = we_s[j * 128 + prow + 8];
            float* acc = (j & 1) ? acc_o : acc_e;
            #pragma unroll
            for (int i = 0; i < 16; ++i) {
                const float w = (i & 2) ? w1 : w0;
                acc[i] = fmaf(w, tmp[i], acc[i]);
            }
        }

        // ---- epilogue: float2 (even, odd) per (o, p) ----
        {
            float* obB = out + (size_t)b * 64 * LOUT_;
            #pragma unroll
            for (int jn = 0; jn < 4; ++jn) {
                #pragma unroll
                for (int e = 0; e < 2; ++e) {
                    int o = og * 32 + jn * 8 + (lane & 3) * 2 + e;
                    float* orow = obB + (size_t)o * LOUT_;
                    *(float2*)(orow + 2 * (size_t)(p0 + prow)) =
                        make_float2(acc_e[4 * jn + e], acc_o[4 * jn + e]);
                    *(float2*)(orow + 2 * (size_t)(p0 + prow + 8)) =
                        make_float2(acc_e[4 * jn + 2 + e], acc_o[4 * jn + 2 + e]);
                }
            }
        }
        __syncthreads();  // XH / we_s reuse next tile
    }
}

extern "C" void kernel_launch(void* const* d_in, const int* in_sizes, int n_in,
                              void* d_out, int out_size) {
    const float* x      = (const float*)d_in[0];
    const float* coords = (const float*)d_in[1];
    const float* sigma  = (const float*)d_in[2];
    const float* weight = (const float*)d_in[3];
    float* out = (float*)d_out;
    (void)in_sizes; (void)n_in; (void)out_size;

    cudaFuncSetAttribute(wct_mma_kernel, cudaFuncAttributeMaxDynamicSharedMemorySize, SMEM_BYTES);

    int dev = 0, sms = 148;
    cudaGetDevice(&dev);
    cudaDeviceGetAttribute(&sms, cudaDevAttrMultiProcessorCount, dev);
    if (sms <= 0) sms = 148;

    wct_mma_kernel<<<sms, THREADS_, SMEM_BYTES>>>(x, coords, sigma, weight, out);
}

// round 12
// speedup vs baseline: 2.4269x; 1.0992x over previous
#include <cuda_runtime.h>
#include <cuda_fp16.h>
#include <cstdint>

// WeightedConvTranspose via mma.sync (fp16 m16n8k16, fp32 accum), parity-decomposed.
// R12 = R11 + parity-specialized 32p x 32o warp tiles + fp16 we-scaling on A-frags:
//   - each warp handles ONE parity (even: 5 taps, odd: 4), B-frags shared across
//     both m16 halves -> ldsm x4 per tile 1728 -> 1152 (-33% L1 wavefronts)
//   - radial weight applied by HMUL2 on the A-fragment (frees tmp[16]; MMA
//     accumulates directly into acc[32])
// cp.async double-buffered staging as R11.

#define B_       8
#define NIN_     16384
#define LOUT_    32768
#define PT_      128
#define THREADS_ 512
#define TILES_   (B_ * (NIN_ / PT_))   // 1024

#define XSP_     132                    // x stage pitch (floats)
#define CSP_     264

// ---- SMEM layout (bytes) ----
#define OFF_W    0                      // 9 chunks x 8192 (fp16 W) = 73728
#define WCH_(j)  (OFF_W + (j) * 8192)
#define OFF_XHI  73728                  // XH: 132 rows x 128B = 16896
#define OFF_XS   90624                  // 2 bufs x 64*132*4 = 2 x 33792
#define OFF_CSB  158208                 // 2 bufs x 3*264*4  = 2 x 3168
#define OFF_WE   164544                 // 9*128*4 = 4608
#define SMEM_BYTES 169152

static __device__ __forceinline__ uint32_t smem_u32(const void* p) {
    uint32_t a;
    asm("{ .reg .u64 t; cvta.to.shared.u64 t, %1; cvt.u32.u64 %0, t; }" : "=r"(a) : "l"(p));
    return a;
}
static __device__ __forceinline__ uint32_t swz128(uint32_t off) {
    return off ^ ((off >> 3) & 0x70);
}
static __device__ __forceinline__ uint32_t cvt_f16x2(float a, float b) {
    uint32_t r;
    asm("cvt.rn.f16x2.f32 %0, %1, %2;" : "=r"(r) : "f"(b), "f"(a));
    return r;
}
static __device__ __forceinline__ uint32_t hmul2u(uint32_t a, uint32_t w) {
    uint32_t r;
    asm("mul.rn.f16x2 %0, %1, %2;" : "=r"(r) : "r"(a), "r"(w));
    return r;
}
static __device__ __forceinline__ void ldsm_x4(uint32_t* r, uint32_t addr) {
    asm volatile("ldmatrix.sync.aligned.m8n8.x4.shared.b16 {%0,%1,%2,%3}, [%4];"
                 : "=r"(r[0]), "=r"(r[1]), "=r"(r[2]), "=r"(r[3]) : "r"(addr));
}
static __device__ __forceinline__ void mma_f16(float* d, const uint32_t* a,
                                               uint32_t b0, uint32_t b1) {
    asm volatile("mma.sync.aligned.m16n8k16.row.col.f32.f16.f16.f32 "
                 "{%0,%1,%2,%3}, {%4,%5,%6,%7}, {%8,%9}, {%0,%1,%2,%3};"
                 : "+f"(d[0]), "+f"(d[1]), "+f"(d[2]), "+f"(d[3])
                 : "r"(a[0]), "r"(a[1]), "r"(a[2]), "r"(a[3]), "r"(b0), "r"(b1));
}
static __device__ __forceinline__ void cp8(uint32_t dst, const float* src, int valid) {
    asm volatile("cp.async.ca.shared.global [%0], [%1], 8, %2;"
                 :: "r"(dst), "l"(src), "r"(valid) : "memory");
}
static __device__ __forceinline__ void cp16(uint32_t dst, const float* src, int valid) {
    asm volatile("cp.async.ca.shared.global [%0], [%1], 16, %2;"
                 :: "r"(dst), "l"(src), "r"(valid) : "memory");
}

__global__ void __launch_bounds__(THREADS_, 1)
wct_mma_kernel(const float* __restrict__ x, const float* __restrict__ coords,
               const float* __restrict__ sigma, const float* __restrict__ weight,
               float* __restrict__ out) {
    extern __shared__ char smem[];
    const uint32_t sb = smem_u32(smem);
    const int tid  = threadIdx.x;
    const int wid  = tid >> 5;
    const int lane = tid & 31;

    float* we_s = (float*)(smem + OFF_WE);

    // ---- one-time W (single fp16): chunk j = W[o][c] for tap j, SW128 rows ----
    for (int idx = tid; idx < 64 * 64 * 9; idx += THREADS_) {
        int j  = idx % 9;
        int oc = idx / 9;
        int c  = oc & 63;
        int o  = oc >> 6;
        __half h = __float2half_rn(weight[oc * 9 + j]);
        uint32_t bo = swz128((uint32_t)o * 128 + (uint32_t)c * 2);
        *(__half*)(smem + WCH_(j) + bo) = h;
    }
    const float rsig = 1.0f / sigma[0];

    // warp tile: 16 warps = 4 p-groups (32p) x 2 o-groups (32o) x 2 parities
    const int par = wid & 1;
    const int og  = (wid >> 1) & 1;
    const int pg  = wid >> 2;
    const int pbase = pg * 32;
    const int prow  = pbase + (lane >> 2);   // h=0 base row
    const int ntap  = 5 - par;

    const uint32_t a_ro0 = (uint32_t)(pbase + (lane & 15)) * 128 + (uint32_t)(lane >> 4) * 16;
    const uint32_t a_ro1 = a_ro0 + 16 * 128;
    const uint32_t b_ro0 = (uint32_t)(og * 32 + (lane & 15)) * 128 + (uint32_t)(lane >> 4) * 16;
    const uint32_t b_ro1 = b_ro0 + 16 * 128;

    // phase-2 convert lane mapping (independent of warp tiling)
    const int bp  = wid * 8 + (lane >> 2);
    const int bc0 = lane & 3;

    // ---- cp.async issue for one tile into buffer 'buf' ----
    auto issue_cp = [&](int ti, int buf) {
        const int b  = ti >> 7;
        const int p0 = (ti & 127) * PT_;
        const float* xb = x + (size_t)b * 64 * NIN_;
        const uint32_t xsd = sb + OFF_XS + (uint32_t)buf * 33792u;
        for (int idx = tid; idx < 64 * 66; idx += THREADS_) {
            int c  = idx / 66;
            int ch = idx - c * 66;
            int xi0 = 2 * ch;
            int g0  = p0 - 2 + xi0;
            int gc  = g0 < 0 ? 0 : (g0 > NIN_ - 2 ? NIN_ - 2 : g0);
            int rem = NIN_ - g0;
            int valid = (g0 < 0) ? 8 : (rem >= 2 ? 8 : (rem == 1 ? 4 : 0));
            cp8(xsd + (uint32_t)(c * XSP_ + xi0) * 4u, xb + (size_t)c * NIN_ + gc, valid);
        }
        const float* cb = coords + (size_t)b * 3 * LOUT_;
        const uint32_t csd = sb + OFF_CSB + (uint32_t)buf * 3168u;
        for (int idx = tid; idx < 3 * 66; idx += THREADS_) {
            int d  = idx / 66;
            int ch = idx - d * 66;
            int k0 = 4 * ch;
            int g0 = 2 * p0 - 4 + k0;
            int gc = g0 < 0 ? 0 : (g0 > LOUT_ - 4 ? LOUT_ - 4 : g0);
            int rem = LOUT_ - g0;
            int valid = (g0 < 0) ? 0 : (rem >= 4 ? 16 : (rem > 0 ? rem * 4 : 0));
            cp16(csd + (uint32_t)(d * CSP_ + k0) * 4u, cb + (size_t)d * LOUT_ + gc, valid);
        }
    };

    __syncthreads();  // W ready

    if ((int)blockIdx.x < TILES_) issue_cp(blockIdx.x, 0);
    asm volatile("cp.async.commit_group;" ::: "memory");

    int it = 0;
    for (int ti = blockIdx.x; ti < TILES_; ti += gridDim.x, ++it) {
        const int buf = it & 1;
        const int b   = ti >> 7;
        const int p0  = (ti & 127) * PT_;
        const int nxt = ti + gridDim.x;

        if (nxt < TILES_) {
            issue_cp(nxt, buf ^ 1);
            asm volatile("cp.async.commit_group;" ::: "memory");
            asm volatile("cp.async.wait_group 1;" ::: "memory");
        } else {
            asm volatile("cp.async.commit_group;" ::: "memory");
            asm volatile("cp.async.wait_group 0;" ::: "memory");
        }
        __syncthreads();

        float* xsB  = (float*)(smem + OFF_XS + (uint32_t)buf * 33792u);
        float* cs_s = (float*)(smem + OFF_CSB + (uint32_t)buf * 3168u);

        // left-edge fixup: xi 0,1 correspond to g = -2,-1 -> 0
        if (p0 == 0) {
            if (tid < 64) {
                float* r = xsB + tid * XSP_;
                r[0] = 0.0f; r[1] = 0.0f;
            }
            __syncthreads();
        }

        // ---- phase 2: convert x[c][xi] -> XH[xi][c] fp16 (SW128), compute we ----
        {
            const uint32_t m = ((uint32_t)bp & 7) << 4;
            char* hbase = smem + OFF_XHI + bp * 128;
            #pragma unroll
            for (int rr = 0; rr < 4; ++rr) {
                int c0 = bc0 * 4 + rr * 16;
                float a0 = xsB[(c0 + 0) * XSP_ + bp];
                float a1 = xsB[(c0 + 1) * XSP_ + bp];
                float a2 = xsB[(c0 + 2) * XSP_ + bp];
                float a3 = xsB[(c0 + 3) * XSP_ + bp];
                uint32_t h0 = cvt_f16x2(a0, a1);
                uint32_t h1 = cvt_f16x2(a2, a3);
                uint32_t d = ((uint32_t)c0 * 2) ^ m;
                *(uint2*)(hbase + d) = make_uint2(h0, h1);
            }
            if (tid < 64) {                            // tail rows 128..131
                int row = 128 + (tid >> 4);
                int c0  = (tid & 15) * 4;
                const uint32_t m2 = ((uint32_t)row & 7) << 4;
                float a0 = xsB[(c0 + 0) * XSP_ + row];
                float a1 = xsB[(c0 + 1) * XSP_ + row];
                float a2 = xsB[(c0 + 2) * XSP_ + row];
                float a3 = xsB[(c0 + 3) * XSP_ + row];
                uint32_t h0 = cvt_f16x2(a0, a1);
                uint32_t h1 = cvt_f16x2(a2, a3);
                uint32_t d = ((uint32_t)c0 * 2) ^ m2;
                *(uint2*)(smem + OFF_XHI + row * 128 + d) = make_uint2(h0, h1);
            }
        }
        // radial weights we[j][p] for l = 2p + (j&1)
        for (int idx = tid; idx < 9 * 128; idx += THREADS_) {
            int j = idx >> 7;
            int p = idx & 127;
            int pr = j & 1;
            int kt = 2 * p + pr + j;
            int kc = 2 * p + pr + 4;
            float dx = cs_s[kt] - cs_s[kc];
            float dy = cs_s[CSP_ + kt] - cs_s[CSP_ + kc];
            float dz = cs_s[2 * CSP_ + kt] - cs_s[2 * CSP_ + kc];
            float nn = sqrtf(fmaf(dx, dx, fmaf(dy, dy, dz * dz)));
            we_s[idx] = fmaxf(1.0f - nn * rsig, 0.0f);
        }
        __syncthreads();

        // ---- phase 3: parity-specialized taps, MMA direct into acc ----
        float acc[32];
        #pragma unroll
        for (int i = 0; i < 32; ++i) acc[i] = 0.0f;

        const uint32_t xhi_b = sb + OFF_XHI;

        #pragma unroll 1
        for (int t = 0; t < ntap; ++t) {
            const int j    = 2 * t + par;
            const int toff = t + par;
            const uint32_t aoff = (uint32_t)toff * 128;
            const uint32_t wch  = sb + (uint32_t)WCH_(j);

            const float* wj = we_s + j * 128;
            uint32_t w0 = cvt_f16x2(wj[prow],      wj[prow]);
            uint32_t w1 = cvt_f16x2(wj[prow + 8],  wj[prow + 8]);
            uint32_t w2 = cvt_f16x2(wj[prow + 16], wj[prow + 16]);
            uint32_t w3 = cvt_f16x2(wj[prow + 24], wj[prow + 24]);

            #pragma unroll
            for (int k16 = 0; k16 < 4; ++k16) {
                const uint32_t kb = (uint32_t)k16 * 32;
                uint32_t a0[4], a1[4];
                ldsm_x4(a0, xhi_b + swz128(a_ro0 + aoff + kb));
                ldsm_x4(a1, xhi_b + swz128(a_ro1 + aoff + kb));
                a0[0] = hmul2u(a0[0], w0); a0[2] = hmul2u(a0[2], w0);
                a0[1] = hmul2u(a0[1], w1); a0[3] = hmul2u(a0[3], w1);
                a1[0] = hmul2u(a1[0], w2); a1[2] = hmul2u(a1[2], w2);
                a1[1] = hmul2u(a1[1], w3); a1[3] = hmul2u(a1[3], w3);
                uint32_t r0[4], r1[4];
                ldsm_x4(r0, wch + swz128(b_ro0 + kb));
                ldsm_x4(r1, wch + swz128(b_ro1 + kb));
                mma_f16(acc + 0,  a0, r0[0], r0[2]);
                mma_f16(acc + 4,  a0, r0[1], r0[3]);
                mma_f16(acc + 8,  a0, r1[0], r1[2]);
                mma_f16(acc + 12, a0, r1[1], r1[3]);
                mma_f16(acc + 16, a1, r0[0], r0[2]);
                mma_f16(acc + 20, a1, r0[1], r0[3]);
                mma_f16(acc + 24, a1, r1[0], r1[2]);
                mma_f16(acc + 28, a1, r1[1], r1[3]);
            }
        }

        // ---- epilogue: scalar stores, one parity per warp ----
        {
            float* obB = out + (size_t)b * 64 * LOUT_;
            #pragma unroll
            for (int h = 0; h < 2; ++h) {
                const int pr = pbase + h * 16 + (lane >> 2);
                const size_t l0 = 2 * (size_t)(p0 + pr) + par;
                #pragma unroll
                for (int jn = 0; jn < 4; ++jn) {
                    const int o = og * 32 + jn * 8 + (lane & 3) * 2;
                    float* orow = obB + (size_t)o * LOUT_;
                    const float* a = acc + h * 16 + jn * 4;
                    orow[l0]              = a[0];
                    orow[LOUT_ + l0]      = a[1];
                    orow[l0 + 16]         = a[2];
                    orow[LOUT_ + l0 + 16] = a[3];
                }
            }
        }
        __syncthreads();  // XH / we_s reuse next tile
    }
}

extern "C" void kernel_launch(void* const* d_in, const int* in_sizes, int n_in,
                              void* d_out, int out_size) {
    const float* x      = (const float*)d_in[0];
    const float* coords = (const float*)d_in[1];
    const float* sigma  = (const float*)d_in[2];
    const float* weight = (const float*)d_in[3];
    float* out = (float*)d_out;
    (void)in_sizes; (void)n_in; (void)out_size;

    cudaFuncSetAttribute(wct_mma_kernel, cudaFuncAttributeMaxDynamicSharedMemorySize, SMEM_BYTES);

    int dev = 0, sms = 148;
    cudaGetDevice(&dev);
    cudaDeviceGetAttribute(&sms, cudaDevAttrMultiProcessorCount, dev);
    if (sms <= 0) sms = 148;

    wct_mma_kernel<<<sms, THREADS_, SMEM_BYTES>>>(x, coords, sigma, weight, out);
}